// round 5
// baseline (speedup 1.0000x reference)
#include <cuda_runtime.h>
#include <cuda_bf16.h>
#include <cuda_fp8.h>
#include <cstdint>

// Problem constants
#define N_U   1024
#define BATCH 4096
#define H     10
#define INV1023 (1.0f / 1023.0f)

// ---------------------------------------------------------------------------
// Scratch (device globals)
// ---------------------------------------------------------------------------
__device__ float g_colpart[32][N_U];
__device__ float g_colsum[N_U];
__device__ float g_rowsum[N_U];
__device__ float g_F[N_U][H];
__device__ float g_G[N_U][H];
__device__ float g_ACR[3][H];
__device__ __align__(256) float g_NW[N_U * N_U];                 // new_weight [k][n]

// GEMM operands.
// bf16 main pass: Ahi [m][k], Bhi [n][k]
// fp8 corrections: pass1 = Alo8 * Bhi8 (scales 512 * 64 = 2^15)
//                  pass2 = Ahi8 * Blo8 (scales 1 * 32768 = 2^15)
__device__ __align__(256) unsigned short g_Ahi[BATCH * N_U];     // 8 MB bf16
__device__ __align__(256) unsigned char  g_Ahi8[BATCH * N_U];    // 4 MB e4m3(x)
__device__ __align__(256) unsigned char  g_Alo8[BATCH * N_U];    // 4 MB e4m3((x-hi)*512)
__device__ __align__(256) unsigned short g_Bhi[N_U * N_U];       // 2 MB bf16 [n][k]
__device__ __align__(256) unsigned char  g_Bhi8[N_U * N_U];      // 1 MB e4m3(v*64)
__device__ __align__(256) unsigned char  g_Blo8[N_U * N_U];      // 1 MB e4m3((v-hi)*32768)

// ---------------------------------------------------------------------------
// Helpers
// ---------------------------------------------------------------------------
__device__ __forceinline__ uint32_t smem_u32(const void* p) {
    uint32_t a;
    asm("{ .reg .u64 t; cvta.to.shared.u64 t, %1; cvt.u32.u64 %0, t; }" : "=r"(a) : "l"(p));
    return a;
}
__device__ __forceinline__ unsigned short bf16u(float x) {
    return __bfloat16_as_ushort(__float2bfloat16_rn(x));
}
__device__ __forceinline__ float bf16f(float x) {
    return __bfloat162float(__float2bfloat16_rn(x));
}
__device__ __forceinline__ unsigned char fp8u(float x) {
    return (unsigned char)__nv_cvt_float_to_fp8(x, __NV_SATFINITE, __NV_E4M3);
}

#define CP_ASYNC16(dst, src) \
    asm volatile("cp.async.cg.shared.global [%0], [%1], 16;" :: "r"(dst), "l"(src))
#define CP_COMMIT() asm volatile("cp.async.commit_group;")
#define CP_WAIT(n)  asm volatile("cp.async.wait_group %0;" :: "n"(n))

#define LDMATRIX_X4(r0, r1, r2, r3, addr) \
    asm volatile("ldmatrix.sync.aligned.m8n8.x4.shared.b16 {%0,%1,%2,%3}, [%4];" \
        : "=r"(r0), "=r"(r1), "=r"(r2), "=r"(r3) : "r"(addr))

#define MMA_BF16(c0, c1, c2, c3, a0, a1, a2, a3, b0, b1) \
    asm volatile("mma.sync.aligned.m16n8k16.row.col.f32.bf16.bf16.f32 " \
        "{%0,%1,%2,%3}, {%4,%5,%6,%7}, {%8,%9}, {%0,%1,%2,%3};" \
        : "+f"(c0), "+f"(c1), "+f"(c2), "+f"(c3) \
        : "r"(a0), "r"(a1), "r"(a2), "r"(a3), "r"(b0), "r"(b1))

#define MMA_E4M3(c0, c1, c2, c3, a0, a1, a2, a3, b0, b1) \
    asm volatile("mma.sync.aligned.m16n8k32.row.col.f32.e4m3.e4m3.f32 " \
        "{%0,%1,%2,%3}, {%4,%5,%6,%7}, {%8,%9}, {%0,%1,%2,%3};" \
        : "+f"(c0), "+f"(c1), "+f"(c2), "+f"(c3) \
        : "r"(a0), "r"(a1), "r"(a2), "r"(a3), "r"(b0), "r"(b1))

// ---------------------------------------------------------------------------
// Split X -> g_Ahi (bf16), g_Ahi8 (e4m3(x)), g_Alo8 (e4m3((x-hi)*512))
// ---------------------------------------------------------------------------
__global__ void __launch_bounds__(256) split_x_kernel(const float* __restrict__ X) {
    int gid = blockIdx.x * 256 + threadIdx.x;
    int idx = gid * 4;
    float4 v = *(const float4*)(X + idx);
    uint32_t hi01 = (uint32_t)bf16u(v.x) | ((uint32_t)bf16u(v.y) << 16);
    uint32_t hi23 = (uint32_t)bf16u(v.z) | ((uint32_t)bf16u(v.w) << 16);
    *(uint2*)(g_Ahi + idx) = make_uint2(hi01, hi23);
    uint32_t h8 = (uint32_t)fp8u(v.x) | ((uint32_t)fp8u(v.y) << 8)
                | ((uint32_t)fp8u(v.z) << 16) | ((uint32_t)fp8u(v.w) << 24);
    uint32_t l8 = (uint32_t)fp8u((v.x - bf16f(v.x)) * 512.f)
                | ((uint32_t)fp8u((v.y - bf16f(v.y)) * 512.f) << 8)
                | ((uint32_t)fp8u((v.z - bf16f(v.z)) * 512.f) << 16)
                | ((uint32_t)fp8u((v.w - bf16f(v.w)) * 512.f) << 24);
    *(uint32_t*)(g_Ahi8 + idx) = h8;
    *(uint32_t*)(g_Alo8 + idx) = l8;
}

// ---------------------------------------------------------------------------
// Fused: column partial sums (blocks 0..127), row sums (128..1151),
// precompute F/G/ACR (1152..1232)
// ---------------------------------------------------------------------------
__global__ void __launch_bounds__(256) fused_sums_kernel(const float* __restrict__ W,
                                                         const float* __restrict__ W1,
                                                         const float* __restrict__ b1) {
    int b = blockIdx.x;
    int tid = threadIdx.x;
    if (b < 128) {
        int rg  = b >> 2;
        int col = (b & 3) * 256 + tid;
        int r0  = rg * 32;
        float s = 0.f;
#pragma unroll
        for (int r = 0; r < 32; r++) s += W[(r0 + r) * N_U + col];
        g_colpart[rg][col] = s;
    } else if (b < 128 + 1024) {
        __shared__ float red[8];
        int row = b - 128;
        float4 v = *(const float4*)(W + row * N_U + tid * 4);
        float s = v.x + v.y + v.z + v.w;
#pragma unroll
        for (int o = 16; o > 0; o >>= 1) s += __shfl_xor_sync(0xffffffffu, s, o);
        if ((tid & 31) == 0) red[tid >> 5] = s;
        __syncthreads();
        if (tid == 0) {
            float t = 0.f;
#pragma unroll
            for (int i = 0; i < 8; i++) t += red[i];
            g_rowsum[row] = t;
        }
    } else {
        int idx = (b - 1152) * 256 + tid;
        if (idx < N_U * H) {
            int i = idx / H, h = idx % H;
            float acc = 0.f;
#pragma unroll
            for (int t = 0; t < 10; t++) {
                float coef = W1[(3 + t) * H + h] + W1[(43 + t) * H + h]
                           - W1[(23 + t) * H + h] * INV1023;
                if ((i >> (9 - t)) & 1) acc += coef;
            }
            g_F[i][h] = acc;
        } else if (idx < 2 * N_U * H) {
            int r = idx - N_U * H;
            int j = r / H, h = r % H;
            float acc = b1[h];
#pragma unroll
            for (int s = 0; s < 10; s++) {
                float coef = W1[(13 + s) * H + h] + W1[(33 + s) * H + h]
                           - W1[(53 + s) * H + h] * INV1023;
                if ((j >> (9 - s)) & 1) acc += coef;
                acc += (512.f * INV1023) * (W1[(23 + s) * H + h] + W1[(53 + s) * H + h]);
            }
            g_G[j][h] = acc;
        } else if (idx < 2 * N_U * H + H) {
            int h = idx - 2 * N_U * H;
            g_ACR[0][h] = W1[h] - (W1[H + h] + W1[2 * H + h]) * INV1023;
            g_ACR[1][h] = W1[H + h] * INV1023;
            g_ACR[2][h] = W1[2 * H + h] * INV1023;
        }
    }
}

__global__ void __launch_bounds__(256) colsum_kernel() {
    int col = blockIdx.x * 256 + threadIdx.x;
    float s = 0.f;
#pragma unroll
    for (int b = 0; b < 32; b++) s += g_colpart[b][col];
    g_colsum[col] = s;
}

// ---------------------------------------------------------------------------
// Per-cell MLP -> g_NW
// ---------------------------------------------------------------------------
__global__ void __launch_bounds__(256) mlp_kernel(const float* __restrict__ W,
                                                  const float* __restrict__ W2,
                                                  const float* __restrict__ b2,
                                                  const float* __restrict__ W3,
                                                  const float* __restrict__ b3) {
    __shared__ float sW2[H * H], sB2[H], sW3[H], sF[H];
    __shared__ float sA[H], sC[H], sR[H];
    __shared__ float sb3;
    int tid = threadIdx.x, i = blockIdx.x;
    if (tid < H * H) sW2[tid] = W2[tid];
    if (tid < H) {
        sB2[tid] = b2[tid];
        sW3[tid] = W3[tid * 21];
        sF[tid]  = g_F[i][tid];
        sA[tid]  = g_ACR[0][tid];
        sC[tid]  = g_ACR[1][tid];
        sR[tid]  = g_ACR[2][tid];
    }
    if (tid == 0) sb3 = b3[0];
    __syncthreads();

    float rs = g_rowsum[i];
#pragma unroll
    for (int c = 0; c < 4; c++) {
        int j = c * 256 + tid;
        float w  = W[i * N_U + j];
        float cs = g_colsum[j];
        float z[H];
#pragma unroll
        for (int h = 0; h < H; h++) {
            float v = fmaf(sA[h], w, fmaf(sC[h], cs, fmaf(sR[h], rs, sF[h] + g_G[j][h])));
            z[h] = fmaxf(v, 0.f);
        }
        float upd = sb3;
#pragma unroll
        for (int k = 0; k < H; k++) {
            float y = sB2[k];
#pragma unroll
            for (int h = 0; h < H; h++) y = fmaf(z[h], sW2[h * H + k], y);
            upd = fmaf(fmaxf(y, 0.f), sW3[k], upd);
        }
        g_NW[i * N_U + j] = w + upd;
    }
}

// ---------------------------------------------------------------------------
// Transpose + split NW -> g_Bhi (bf16), g_Bhi8 (e4m3(v*64)), g_Blo8 (e4m3(lo*32768))
// ---------------------------------------------------------------------------
__global__ void __launch_bounds__(256) transpose_split_kernel() {
    __shared__ float tile[32][33];
    int bx = blockIdx.x, by = blockIdx.y;
    int tx = threadIdx.x, ty = threadIdx.y;           // 32 x 8
    int i0 = by * 32, j0 = bx * 32;
#pragma unroll
    for (int r = 0; r < 4; r++)
        tile[ty * 4 + r][tx] = g_NW[(i0 + ty * 4 + r) * N_U + j0 + tx];
    __syncthreads();
#pragma unroll
    for (int r = 0; r < 4; r++) {
        int j = j0 + ty * 4 + r;
        int i = i0 + tx;
        float v  = tile[tx][ty * 4 + r];
        float hi = bf16f(v);
        g_Bhi[j * N_U + i]  = bf16u(v);
        g_Bhi8[j * N_U + i] = fp8u(v * 64.f);
        g_Blo8[j * N_U + i] = fp8u((v - hi) * 32768.f);
    }
}

// ---------------------------------------------------------------------------
// GEMM: out = relu( Ahi*Bhi + (Alo8*Bhi8 + Ahi8*Blo8) * 2^-15 )
// BM=128, BN=256, 256 threads (8 warps, 2m x 4n), warp tile 64x64.
// 64 iterations, each consuming 64 bytes of K per row:
//   iters  0..15 : fp8 pass1 (Alo8 x Bhi8), K=64 e4m3/iter
//   iters 16..31 : fp8 pass2 (Ahi8 x Blo8)
//   (scale accumulators by 2^-15 after iter 31)
//   iters 32..63 : bf16 main (Ahi x Bhi), K=32 bf16/iter
// 4-stage cp.async pipeline; smem rows padded to 80B (64B payload).
// ---------------------------------------------------------------------------
#define BM 128
#define BN 256
#define STAGES 4
#define AROWB 80
#define ABYTES (BM * AROWB)              // 10240
#define BBYTES (BN * AROWB)              // 20480
#define STBYTES (ABYTES + BBYTES)        // 30720
#define SMEM_GEMM (STAGES * STBYTES)     // 122880

__global__ void __launch_bounds__(256, 1) gemm_mma_kernel(float* __restrict__ out) {
    extern __shared__ char smem[];
    uint32_t sb = smem_u32(smem);
    int tid  = threadIdx.x;
    int wid  = tid >> 5;
    int lane = tid & 31;

    int mt = blockIdx.x & 31;            // 32 m-tiles
    int nt = blockIdx.x >> 5;            // 4 n-tiles
    int mw = wid & 1;                    // warp m (2)
    int nw = wid >> 1;                   // warp n (4)

    // Segment tables (byte pointers + byte row strides)
    const char* Asrc[3];
    const char* Bsrc[3];
    int Astr[3], Bstr[3];
    Asrc[0] = (const char*)g_Alo8 + (size_t)(mt * BM) * 1024;  Astr[0] = 1024;
    Asrc[1] = (const char*)g_Ahi8 + (size_t)(mt * BM) * 1024;  Astr[1] = 1024;
    Asrc[2] = (const char*)g_Ahi  + (size_t)(mt * BM) * 2048;  Astr[2] = 2048;
    Bsrc[0] = (const char*)g_Bhi8 + (size_t)(nt * BN) * 1024;  Bstr[0] = 1024;
    Bsrc[1] = (const char*)g_Blo8 + (size_t)(nt * BN) * 1024;  Bstr[1] = 1024;
    Bsrc[2] = (const char*)g_Bhi  + (size_t)(nt * BN) * 2048;  Bstr[2] = 2048;

    float c[4][8][4];
#pragma unroll
    for (int f = 0; f < 4; f++)
#pragma unroll
        for (int n = 0; n < 8; n++)
#pragma unroll
            for (int q = 0; q < 4; q++) c[f][n][q] = 0.f;

    const int ITERS = 64;

    auto load_stage = [&](int it, int st) {
        int seg = (it < 16) ? 0 : ((it < 32) ? 1 : 2);
        int kb  = (it - ((seg == 0) ? 0 : (seg == 1) ? 16 : 32)) * 64;  // byte offset
        uint32_t abase = sb + st * STBYTES;
        uint32_t bbase = abase + ABYTES;
        const char* Ag = Asrc[seg];
        const char* Bg = Bsrc[seg];
        int as = Astr[seg], bs = Bstr[seg];
#pragma unroll
        for (int q = 0; q < 2; q++) {                // A: 512 16B chunks
            int chunk = tid + q * 256;
            int row = chunk >> 2;
            int off = (chunk & 3) * 16;
            CP_ASYNC16(abase + row * AROWB + off, Ag + (size_t)row * as + kb + off);
        }
#pragma unroll
        for (int q = 0; q < 4; q++) {                // B: 1024 16B chunks
            int chunk = tid + q * 256;
            int row = chunk >> 2;
            int off = (chunk & 3) * 16;
            CP_ASYNC16(bbase + row * AROWB + off, Bg + (size_t)row * bs + kb + off);
        }
    };

#pragma unroll
    for (int s = 0; s < STAGES - 1; s++) {
        load_stage(s, s);
        CP_COMMIT();
    }

    int lrow = lane & 15;
    int lcol = (lane >> 4) * 16;

    for (int i = 0; i < ITERS; i++) {
        CP_WAIT(2);
        __syncthreads();

        int nx = i + STAGES - 1;
        if (nx < ITERS) load_stage(nx, nx & (STAGES - 1));
        CP_COMMIT();

        int st = i & (STAGES - 1);
        uint32_t abase = sb + st * STBYTES;
        uint32_t bbase = abase + ABYTES;

#pragma unroll
        for (int ks = 0; ks < 2; ks++) {
            uint32_t a[4][4];
#pragma unroll
            for (int f = 0; f < 4; f++)
                LDMATRIX_X4(a[f][0], a[f][1], a[f][2], a[f][3],
                    abase + (mw * 64 + f * 16 + lrow) * AROWB + ks * 32 + lcol);
            uint32_t b[8][2];
#pragma unroll
            for (int g = 0; g < 4; g++) {
                uint32_t r0, r1, r2, r3;
                LDMATRIX_X4(r0, r1, r2, r3,
                    bbase + (nw * 64 + g * 16 + lrow) * AROWB + ks * 32 + lcol);
                b[2 * g][0] = r0;  b[2 * g][1] = r2;
                b[2 * g + 1][0] = r1;  b[2 * g + 1][1] = r3;
            }
            if (i < 32) {
#pragma unroll
                for (int f = 0; f < 4; f++)
#pragma unroll
                    for (int n = 0; n < 8; n++)
                        MMA_E4M3(c[f][n][0], c[f][n][1], c[f][n][2], c[f][n][3],
                                 a[f][0], a[f][1], a[f][2], a[f][3], b[n][0], b[n][1]);
            } else {
#pragma unroll
                for (int f = 0; f < 4; f++)
#pragma unroll
                    for (int n = 0; n < 8; n++)
                        MMA_BF16(c[f][n][0], c[f][n][1], c[f][n][2], c[f][n][3],
                                 a[f][0], a[f][1], a[f][2], a[f][3], b[n][0], b[n][1]);
            }
        }
        if (i == 31) {
            const float s15 = 1.f / 32768.f;
#pragma unroll
            for (int f = 0; f < 4; f++)
#pragma unroll
                for (int n = 0; n < 8; n++)
#pragma unroll
                    for (int q = 0; q < 4; q++) c[f][n][q] *= s15;
        }
        __syncthreads();
    }

    // Epilogue: relu + store
    int rbase = mt * BM + mw * 64 + (lane >> 2);
    int cbase = nt * BN + nw * 64 + (lane & 3) * 2;
#pragma unroll
    for (int f = 0; f < 4; f++) {
#pragma unroll
        for (int n = 0; n < 8; n++) {
            int r = rbase + f * 16;
            int cc = cbase + n * 8;
            float2 v0, v1;
            v0.x = fmaxf(c[f][n][0], 0.f);
            v0.y = fmaxf(c[f][n][1], 0.f);
            v1.x = fmaxf(c[f][n][2], 0.f);
            v1.y = fmaxf(c[f][n][3], 0.f);
            *(float2*)(out + (size_t)r * N_U + cc)       = v0;
            *(float2*)(out + (size_t)(r + 8) * N_U + cc) = v1;
        }
    }
}

// ---------------------------------------------------------------------------
// Row softmax in-place
// ---------------------------------------------------------------------------
__global__ void __launch_bounds__(256) softmax_kernel(float* __restrict__ out) {
    __shared__ float redm[8];
    __shared__ float reds[8];
    __shared__ float bval[2];
    int row = blockIdx.x, tid = threadIdx.x;
    int lane = tid & 31, wid = tid >> 5;

    float4 v = *(float4*)(out + row * N_U + tid * 4);
    float m = fmaxf(fmaxf(v.x, v.y), fmaxf(v.z, v.w));
#pragma unroll
    for (int o = 16; o > 0; o >>= 1) m = fmaxf(m, __shfl_xor_sync(0xffffffffu, m, o));
    if (lane == 0) redm[wid] = m;
    __syncthreads();
    if (tid == 0) {
        float t = redm[0];
#pragma unroll
        for (int i = 1; i < 8; i++) t = fmaxf(t, redm[i]);
        bval[0] = t;
    }
    __syncthreads();
    m = bval[0];
    v.x = expf(v.x - m); v.y = expf(v.y - m);
    v.z = expf(v.z - m); v.w = expf(v.w - m);
    float s = v.x + v.y + v.z + v.w;
#pragma unroll
    for (int o = 16; o > 0; o >>= 1) s += __shfl_xor_sync(0xffffffffu, s, o);
    if (lane == 0) reds[wid] = s;
    __syncthreads();
    if (tid == 0) {
        float t = 0.f;
#pragma unroll
        for (int i = 0; i < 8; i++) t += reds[i];
        bval[1] = 1.f / t;
    }
    __syncthreads();
    float inv = bval[1];
    v.x *= inv; v.y *= inv; v.z *= inv; v.w *= inv;
    *(float4*)(out + row * N_U + tid * 4) = v;
}

// ---------------------------------------------------------------------------
// Entry point — GEMM is the 6th launch so ncu (-s 5 -c 1) profiles it.
// ---------------------------------------------------------------------------
extern "C" void kernel_launch(void* const* d_in, const int* in_sizes, int n_in,
                              void* d_out, int out_size) {
    const float* X      = (const float*)d_in[0];
    const float* weight = (const float*)d_in[1];
    const float* W1     = (const float*)d_in[3];
    const float* b1     = (const float*)d_in[4];
    const float* W2     = (const float*)d_in[5];
    const float* b2     = (const float*)d_in[6];
    const float* W3     = (const float*)d_in[7];
    const float* b3     = (const float*)d_in[8];
    float* out = (float*)d_out;

    static bool attr_done = false;
    if (!attr_done) {
        cudaFuncSetAttribute(gemm_mma_kernel,
                             cudaFuncAttributeMaxDynamicSharedMemorySize, SMEM_GEMM);
        attr_done = true;
    }

    split_x_kernel<<<BATCH * N_U / 1024, 256>>>(X);                     // 1
    fused_sums_kernel<<<128 + 1024 + 81, 256>>>(weight, W1, b1);        // 2
    colsum_kernel<<<4, 256>>>();                                        // 3
    mlp_kernel<<<N_U, 256>>>(weight, W2, b2, W3, b3);                   // 4
    transpose_split_kernel<<<dim3(32, 32), dim3(32, 8)>>>();            // 5
    gemm_mma_kernel<<<128, 256, SMEM_GEMM>>>(out);                      // 6  <- profiled
    softmax_kernel<<<BATCH, 256>>>(out);                                // 7
}

// round 6
// speedup vs baseline: 1.0878x; 1.0878x over previous
#include <cuda_runtime.h>
#include <cuda_bf16.h>
#include <cstdint>

// Problem constants
#define N_U   1024
#define BATCH 4096
#define H     10
#define INV1023 (1.0f / 1023.0f)

// ---------------------------------------------------------------------------
// Scratch (device globals)
// ---------------------------------------------------------------------------
__device__ float g_colpart[32][N_U];
__device__ float g_colsum[N_U];
__device__ float g_rowsum[N_U];
__device__ float g_F[N_U][H];
__device__ float g_G[N_U][H];
__device__ float g_ACR[3][H];
__device__ __align__(256) float g_NW[N_U * N_U];                 // new_weight [k][n]

// Split operands (bf16 as ushort), deduped: A hi used by segs 1 & 2.
__device__ __align__(256) unsigned short g_Ahi[BATCH * N_U];     // 8 MB
__device__ __align__(256) unsigned short g_Alo[BATCH * N_U];     // 8 MB
__device__ __align__(256) unsigned short g_Bhi[N_U * N_U];       // 2 MB  [n][k]
__device__ __align__(256) unsigned short g_Blo[N_U * N_U];       // 2 MB  [n][k]

// ---------------------------------------------------------------------------
// Helpers
// ---------------------------------------------------------------------------
__device__ __forceinline__ uint32_t smem_u32(const void* p) {
    uint32_t a;
    asm("{ .reg .u64 t; cvta.to.shared.u64 t, %1; cvt.u32.u64 %0, t; }" : "=r"(a) : "l"(p));
    return a;
}
__device__ __forceinline__ unsigned short bf16u(float x) {
    return __bfloat16_as_ushort(__float2bfloat16_rn(x));
}
__device__ __forceinline__ float bf16f(float x) {
    return __bfloat162float(__float2bfloat16_rn(x));
}

#define CP_ASYNC16(dst, src) \
    asm volatile("cp.async.cg.shared.global [%0], [%1], 16;" :: "r"(dst), "l"(src))
#define CP_COMMIT() asm volatile("cp.async.commit_group;")
#define CP_WAIT(n)  asm volatile("cp.async.wait_group %0;" :: "n"(n))

#define LDMATRIX_X4(r0, r1, r2, r3, addr) \
    asm volatile("ldmatrix.sync.aligned.m8n8.x4.shared.b16 {%0,%1,%2,%3}, [%4];" \
        : "=r"(r0), "=r"(r1), "=r"(r2), "=r"(r3) : "r"(addr))

#define MMA_BF16(c0, c1, c2, c3, a0, a1, a2, a3, b0, b1) \
    asm volatile("mma.sync.aligned.m16n8k16.row.col.f32.bf16.bf16.f32 " \
        "{%0,%1,%2,%3}, {%4,%5,%6,%7}, {%8,%9}, {%0,%1,%2,%3};" \
        : "+f"(c0), "+f"(c1), "+f"(c2), "+f"(c3) \
        : "r"(a0), "r"(a1), "r"(a2), "r"(a3), "r"(b0), "r"(b1))

// ---------------------------------------------------------------------------
// Split X -> g_Ahi/g_Alo [m][k]
// ---------------------------------------------------------------------------
__global__ void __launch_bounds__(256) split_x_kernel(const float* __restrict__ X) {
    int gid = blockIdx.x * 256 + threadIdx.x;
    int idx = gid * 4;
    float4 v = *(const float4*)(X + idx);
    uint32_t hi01 = (uint32_t)bf16u(v.x) | ((uint32_t)bf16u(v.y) << 16);
    uint32_t hi23 = (uint32_t)bf16u(v.z) | ((uint32_t)bf16u(v.w) << 16);
    uint32_t lo01 = (uint32_t)bf16u(v.x - bf16f(v.x)) | ((uint32_t)bf16u(v.y - bf16f(v.y)) << 16);
    uint32_t lo23 = (uint32_t)bf16u(v.z - bf16f(v.z)) | ((uint32_t)bf16u(v.w - bf16f(v.w)) << 16);
    *(uint2*)(g_Ahi + idx) = make_uint2(hi01, hi23);
    *(uint2*)(g_Alo + idx) = make_uint2(lo01, lo23);
}

// ---------------------------------------------------------------------------
// Fused: column partial sums (blocks 0..127), row sums (128..1151),
// precompute F/G/ACR (1152..1232)
// ---------------------------------------------------------------------------
__global__ void __launch_bounds__(256) fused_sums_kernel(const float* __restrict__ W,
                                                         const float* __restrict__ W1,
                                                         const float* __restrict__ b1) {
    int b = blockIdx.x;
    int tid = threadIdx.x;
    if (b < 128) {
        int rg  = b >> 2;
        int col = (b & 3) * 256 + tid;
        int r0  = rg * 32;
        float s = 0.f;
#pragma unroll
        for (int r = 0; r < 32; r++) s += W[(r0 + r) * N_U + col];
        g_colpart[rg][col] = s;
    } else if (b < 128 + 1024) {
        __shared__ float red[8];
        int row = b - 128;
        float4 v = *(const float4*)(W + row * N_U + tid * 4);
        float s = v.x + v.y + v.z + v.w;
#pragma unroll
        for (int o = 16; o > 0; o >>= 1) s += __shfl_xor_sync(0xffffffffu, s, o);
        if ((tid & 31) == 0) red[tid >> 5] = s;
        __syncthreads();
        if (tid == 0) {
            float t = 0.f;
#pragma unroll
            for (int i = 0; i < 8; i++) t += red[i];
            g_rowsum[row] = t;
        }
    } else {
        int idx = (b - 1152) * 256 + tid;
        if (idx < N_U * H) {
            int i = idx / H, h = idx % H;
            float acc = 0.f;
#pragma unroll
            for (int t = 0; t < 10; t++) {
                float coef = W1[(3 + t) * H + h] + W1[(43 + t) * H + h]
                           - W1[(23 + t) * H + h] * INV1023;
                if ((i >> (9 - t)) & 1) acc += coef;
            }
            g_F[i][h] = acc;
        } else if (idx < 2 * N_U * H) {
            int r = idx - N_U * H;
            int j = r / H, h = r % H;
            float acc = b1[h];
#pragma unroll
            for (int s = 0; s < 10; s++) {
                float coef = W1[(13 + s) * H + h] + W1[(33 + s) * H + h]
                           - W1[(53 + s) * H + h] * INV1023;
                if ((j >> (9 - s)) & 1) acc += coef;
                acc += (512.f * INV1023) * (W1[(23 + s) * H + h] + W1[(53 + s) * H + h]);
            }
            g_G[j][h] = acc;
        } else if (idx < 2 * N_U * H + H) {
            int h = idx - 2 * N_U * H;
            g_ACR[0][h] = W1[h] - (W1[H + h] + W1[2 * H + h]) * INV1023;
            g_ACR[1][h] = W1[H + h] * INV1023;
            g_ACR[2][h] = W1[2 * H + h] * INV1023;
        }
    }
}

__global__ void __launch_bounds__(256) colsum_kernel() {
    int col = blockIdx.x * 256 + threadIdx.x;
    float s = 0.f;
#pragma unroll
    for (int b = 0; b < 32; b++) s += g_colpart[b][col];
    g_colsum[col] = s;
}

// ---------------------------------------------------------------------------
// Per-cell MLP -> g_NW.  One column per thread (low register pressure):
// grid 4096 blocks x 256 threads; block b: i = b>>2, j = (b&3)*256 + tid.
// ---------------------------------------------------------------------------
__global__ void __launch_bounds__(256) mlp_kernel(const float* __restrict__ W,
                                                  const float* __restrict__ W2,
                                                  const float* __restrict__ b2,
                                                  const float* __restrict__ W3,
                                                  const float* __restrict__ b3) {
    __shared__ float sW2[H * H], sB2[H], sW3[H], sF[H];
    __shared__ float sA[H], sC[H], sR[H];
    __shared__ float sb3, srs;
    int tid = threadIdx.x;
    int i  = blockIdx.x >> 2;
    int jt = blockIdx.x & 3;
    if (tid < H * H) sW2[tid] = W2[tid];
    if (tid < H) {
        sB2[tid] = b2[tid];
        sW3[tid] = W3[tid * 21];          // only output column 0 matters
        sF[tid]  = g_F[i][tid];
        sA[tid]  = g_ACR[0][tid];
        sC[tid]  = g_ACR[1][tid];
        sR[tid]  = g_ACR[2][tid];
    }
    if (tid == 0) { sb3 = b3[0]; srs = g_rowsum[i]; }
    __syncthreads();

    int j = jt * 256 + tid;
    float w  = W[i * N_U + j];
    float cs = g_colsum[j];
    float rs = srs;
    float z[H];
#pragma unroll
    for (int h = 0; h < H; h++) {
        float v = fmaf(sA[h], w, fmaf(sC[h], cs, fmaf(sR[h], rs, sF[h] + g_G[j][h])));
        z[h] = fmaxf(v, 0.f);
    }
    float upd = sb3;
#pragma unroll
    for (int k = 0; k < H; k++) {
        float y = sB2[k];
#pragma unroll
        for (int h = 0; h < H; h++) y = fmaf(z[h], sW2[h * H + k], y);
        upd = fmaf(fmaxf(y, 0.f), sW3[k], upd);
    }
    g_NW[i * N_U + j] = w + upd;
}

// ---------------------------------------------------------------------------
// Transpose + split NW -> g_Bhi/g_Blo [n][k]
// ---------------------------------------------------------------------------
__global__ void __launch_bounds__(256) transpose_split_kernel() {
    __shared__ float tile[32][33];
    int bx = blockIdx.x, by = blockIdx.y;
    int tx = threadIdx.x, ty = threadIdx.y;           // 32 x 8
    int i0 = by * 32, j0 = bx * 32;
#pragma unroll
    for (int r = 0; r < 4; r++)
        tile[ty * 4 + r][tx] = g_NW[(i0 + ty * 4 + r) * N_U + j0 + tx];
    __syncthreads();
#pragma unroll
    for (int r = 0; r < 4; r++) {
        int j = j0 + ty * 4 + r;
        int i = i0 + tx;
        float v  = tile[tx][ty * 4 + r];
        float hi = bf16f(v);
        g_Bhi[j * N_U + i] = bf16u(v);
        g_Blo[j * N_U + i] = bf16u(v - hi);
    }
}

// ---------------------------------------------------------------------------
// GEMM: out = relu( Ahi*Bhi + Ahi*Blo + Alo*Bhi ), bf16 mma.sync.
// BM=128, BN=256, BK=32, 256 threads (8 warps, 2m x 4n), warp tile 64x64.
// 4-stage cp.async pipeline; padded smem rows (40 bf16 = 80B) conflict-free.
// Single barrier per iteration (top barrier covers slot-reuse safety).
// ---------------------------------------------------------------------------
#define BM 128
#define BN 256
#define BK 32
#define STAGES 4
#define AROW 40
#define ABYTES (BM * AROW * 2)           // 10240
#define BBYTES (BN * AROW * 2)           // 20480
#define STBYTES (ABYTES + BBYTES)        // 30720
#define SMEM_GEMM (STAGES * STBYTES)     // 122880

__global__ void __launch_bounds__(256, 1) gemm_mma_kernel(float* __restrict__ out) {
    extern __shared__ char smem[];
    uint32_t sb = smem_u32(smem);
    int tid  = threadIdx.x;
    int wid  = tid >> 5;
    int lane = tid & 31;

    int mt = blockIdx.x & 31;            // 32 m-tiles
    int nt = blockIdx.x >> 5;            // 4 n-tiles
    int mw = wid & 1;                    // warp m (2)
    int nw = wid >> 1;                   // warp n (4)

    const unsigned short* Aseg[3];
    const unsigned short* Bseg[3];
    Aseg[0] = g_Ahi + (size_t)(mt * BM) * N_U;
    Aseg[1] = Aseg[0];
    Aseg[2] = g_Alo + (size_t)(mt * BM) * N_U;
    Bseg[0] = g_Bhi + (size_t)(nt * BN) * N_U;
    Bseg[1] = g_Blo + (size_t)(nt * BN) * N_U;
    Bseg[2] = Bseg[0];

    float c[4][8][4];
#pragma unroll
    for (int f = 0; f < 4; f++)
#pragma unroll
        for (int n = 0; n < 8; n++)
#pragma unroll
            for (int q = 0; q < 4; q++) c[f][n][q] = 0.f;

    const int ITERS = 96;

    auto load_stage = [&](int it, int st) {
        int seg = it >> 5;
        int k0  = (it & 31) * BK;
        uint32_t abase = sb + st * STBYTES;
        uint32_t bbase = abase + ABYTES;
        const unsigned short* Ag = Aseg[seg];
        const unsigned short* Bg = Bseg[seg];
#pragma unroll
        for (int q = 0; q < 2; q++) {
            int chunk = tid + q * 256;
            int row = chunk >> 2;
            int off = (chunk & 3) * 8;
            CP_ASYNC16(abase + row * (AROW * 2) + off * 2,
                       (const char*)(Ag + (size_t)row * N_U + k0 + off));
        }
#pragma unroll
        for (int q = 0; q < 4; q++) {
            int chunk = tid + q * 256;
            int row = chunk >> 2;
            int off = (chunk & 3) * 8;
            CP_ASYNC16(bbase + row * (AROW * 2) + off * 2,
                       (const char*)(Bg + (size_t)row * N_U + k0 + off));
        }
    };

#pragma unroll
    for (int s = 0; s < STAGES - 1; s++) {
        load_stage(s, s);
        CP_COMMIT();
    }

    int lrow = lane & 15;
    int lcol = (lane >> 4) * 16;

    for (int i = 0; i < ITERS; i++) {
        CP_WAIT(2);
        __syncthreads();                 // single barrier: data ready + slot reuse safe

        int nx = i + STAGES - 1;
        if (nx < ITERS) load_stage(nx, nx & (STAGES - 1));
        CP_COMMIT();

        int st = i & (STAGES - 1);
        uint32_t abase = sb + st * STBYTES;
        uint32_t bbase = abase + ABYTES;

#pragma unroll
        for (int ks = 0; ks < 2; ks++) {
            uint32_t a[4][4];
#pragma unroll
            for (int f = 0; f < 4; f++)
                LDMATRIX_X4(a[f][0], a[f][1], a[f][2], a[f][3],
                    abase + (mw * 64 + f * 16 + lrow) * (AROW * 2) + ks * 32 + lcol);
            uint32_t b[8][2];
#pragma unroll
            for (int g = 0; g < 4; g++) {
                uint32_t r0, r1, r2, r3;
                LDMATRIX_X4(r0, r1, r2, r3,
                    bbase + (nw * 64 + g * 16 + lrow) * (AROW * 2) + ks * 32 + lcol);
                b[2 * g][0] = r0;  b[2 * g][1] = r2;
                b[2 * g + 1][0] = r1;  b[2 * g + 1][1] = r3;
            }
#pragma unroll
            for (int f = 0; f < 4; f++)
#pragma unroll
                for (int n = 0; n < 8; n++)
                    MMA_BF16(c[f][n][0], c[f][n][1], c[f][n][2], c[f][n][3],
                             a[f][0], a[f][1], a[f][2], a[f][3], b[n][0], b[n][1]);
        }
    }

    // Epilogue: relu + store
    int rbase = mt * BM + mw * 64 + (lane >> 2);
    int cbase = nt * BN + nw * 64 + (lane & 3) * 2;
#pragma unroll
    for (int f = 0; f < 4; f++) {
#pragma unroll
        for (int n = 0; n < 8; n++) {
            int r = rbase + f * 16;
            int cc = cbase + n * 8;
            float2 v0, v1;
            v0.x = fmaxf(c[f][n][0], 0.f);
            v0.y = fmaxf(c[f][n][1], 0.f);
            v1.x = fmaxf(c[f][n][2], 0.f);
            v1.y = fmaxf(c[f][n][3], 0.f);
            *(float2*)(out + (size_t)r * N_U + cc)       = v0;
            *(float2*)(out + (size_t)(r + 8) * N_U + cc) = v1;
        }
    }
}

// ---------------------------------------------------------------------------
// Row softmax in-place
// ---------------------------------------------------------------------------
__global__ void __launch_bounds__(256) softmax_kernel(float* __restrict__ out) {
    __shared__ float redm[8];
    __shared__ float reds[8];
    __shared__ float bval[2];
    int row = blockIdx.x, tid = threadIdx.x;
    int lane = tid & 31, wid = tid >> 5;

    float4 v = *(float4*)(out + row * N_U + tid * 4);
    float m = fmaxf(fmaxf(v.x, v.y), fmaxf(v.z, v.w));
#pragma unroll
    for (int o = 16; o > 0; o >>= 1) m = fmaxf(m, __shfl_xor_sync(0xffffffffu, m, o));
    if (lane == 0) redm[wid] = m;
    __syncthreads();
    if (tid == 0) {
        float t = redm[0];
#pragma unroll
        for (int i = 1; i < 8; i++) t = fmaxf(t, redm[i]);
        bval[0] = t;
    }
    __syncthreads();
    m = bval[0];
    v.x = expf(v.x - m); v.y = expf(v.y - m);
    v.z = expf(v.z - m); v.w = expf(v.w - m);
    float s = v.x + v.y + v.z + v.w;
#pragma unroll
    for (int o = 16; o > 0; o >>= 1) s += __shfl_xor_sync(0xffffffffu, s, o);
    if (lane == 0) reds[wid] = s;
    __syncthreads();
    if (tid == 0) {
        float t = 0.f;
#pragma unroll
        for (int i = 0; i < 8; i++) t += reds[i];
        bval[1] = 1.f / t;
    }
    __syncthreads();
    float inv = bval[1];
    v.x *= inv; v.y *= inv; v.z *= inv; v.w *= inv;
    *(float4*)(out + row * N_U + tid * 4) = v;
}

// ---------------------------------------------------------------------------
// Entry point — GEMM is the 6th launch so ncu (-s 5 -c 1) profiles it.
// ---------------------------------------------------------------------------
extern "C" void kernel_launch(void* const* d_in, const int* in_sizes, int n_in,
                              void* d_out, int out_size) {
    const float* X      = (const float*)d_in[0];
    const float* weight = (const float*)d_in[1];
    const float* W1     = (const float*)d_in[3];
    const float* b1     = (const float*)d_in[4];
    const float* W2     = (const float*)d_in[5];
    const float* b2     = (const float*)d_in[6];
    const float* W3     = (const float*)d_in[7];
    const float* b3     = (const float*)d_in[8];
    float* out = (float*)d_out;

    static bool attr_done = false;
    if (!attr_done) {
        cudaFuncSetAttribute(gemm_mma_kernel,
                             cudaFuncAttributeMaxDynamicSharedMemorySize, SMEM_GEMM);
        attr_done = true;
    }

    split_x_kernel<<<BATCH * N_U / 1024, 256>>>(X);                     // 1
    fused_sums_kernel<<<128 + 1024 + 81, 256>>>(weight, W1, b1);        // 2
    colsum_kernel<<<4, 256>>>();                                        // 3
    mlp_kernel<<<4096, 256>>>(weight, W2, b2, W3, b3);                  // 4
    transpose_split_kernel<<<dim3(32, 32), dim3(32, 8)>>>();            // 5
    gemm_mma_kernel<<<128, 256, SMEM_GEMM>>>(out);                      // 6  <- profiled
    softmax_kernel<<<BATCH, 256>>>(out);                                // 7
}

// round 7
// speedup vs baseline: 1.1548x; 1.0616x over previous
#include <cuda_runtime.h>
#include <cuda_bf16.h>
#include <cstdint>

// Problem constants
#define N_U   1024
#define BATCH 4096
#define H     10
#define INV1023 (1.0f / 1023.0f)

// ---------------------------------------------------------------------------
// Scratch (device globals)
// ---------------------------------------------------------------------------
__device__ float g_colpart[32][N_U];
__device__ float g_colsum[N_U];
__device__ float g_rowsum[N_U];
__device__ float g_F[N_U][H];
__device__ float g_G[N_U][12];            // padded to 12 for float4 loads
__device__ float g_ACR[3][H];
__device__ __align__(256) float g_NW[N_U * N_U];                 // new_weight [k][n]

// Split operands (bf16 as ushort)
__device__ __align__(256) unsigned short g_Ahi[BATCH * N_U];     // 8 MB
__device__ __align__(256) unsigned short g_Alo[BATCH * N_U];     // 8 MB
__device__ __align__(256) unsigned short g_Bhi[N_U * N_U];       // 2 MB  [n][k]
__device__ __align__(256) unsigned short g_Blo[N_U * N_U];       // 2 MB  [n][k]

// ---------------------------------------------------------------------------
// Helpers
// ---------------------------------------------------------------------------
__device__ __forceinline__ uint32_t smem_u32(const void* p) {
    uint32_t a;
    asm("{ .reg .u64 t; cvta.to.shared.u64 t, %1; cvt.u32.u64 %0, t; }" : "=r"(a) : "l"(p));
    return a;
}
__device__ __forceinline__ unsigned short bf16u(float x) {
    return __bfloat16_as_ushort(__float2bfloat16_rn(x));
}
__device__ __forceinline__ float bf16f(float x) {
    return __bfloat162float(__float2bfloat16_rn(x));
}

#define CP_ASYNC16(dst, src) \
    asm volatile("cp.async.cg.shared.global [%0], [%1], 16;" :: "r"(dst), "l"(src))
#define CP_COMMIT() asm volatile("cp.async.commit_group;")
#define CP_WAIT(n)  asm volatile("cp.async.wait_group %0;" :: "n"(n))

#define LDMATRIX_X4(r0, r1, r2, r3, addr) \
    asm volatile("ldmatrix.sync.aligned.m8n8.x4.shared.b16 {%0,%1,%2,%3}, [%4];" \
        : "=r"(r0), "=r"(r1), "=r"(r2), "=r"(r3) : "r"(addr))

#define MMA_BF16(c0, c1, c2, c3, a0, a1, a2, a3, b0, b1) \
    asm volatile("mma.sync.aligned.m16n8k16.row.col.f32.bf16.bf16.f32 " \
        "{%0,%1,%2,%3}, {%4,%5,%6,%7}, {%8,%9}, {%0,%1,%2,%3};" \
        : "+f"(c0), "+f"(c1), "+f"(c2), "+f"(c3) \
        : "r"(a0), "r"(a1), "r"(a2), "r"(a3), "r"(b0), "r"(b1))

// ---------------------------------------------------------------------------
// Split X -> g_Ahi/g_Alo [m][k]
// ---------------------------------------------------------------------------
__global__ void __launch_bounds__(256) split_x_kernel(const float* __restrict__ X) {
    int gid = blockIdx.x * 256 + threadIdx.x;
    int idx = gid * 4;
    float4 v = *(const float4*)(X + idx);
    uint32_t hi01 = (uint32_t)bf16u(v.x) | ((uint32_t)bf16u(v.y) << 16);
    uint32_t hi23 = (uint32_t)bf16u(v.z) | ((uint32_t)bf16u(v.w) << 16);
    uint32_t lo01 = (uint32_t)bf16u(v.x - bf16f(v.x)) | ((uint32_t)bf16u(v.y - bf16f(v.y)) << 16);
    uint32_t lo23 = (uint32_t)bf16u(v.z - bf16f(v.z)) | ((uint32_t)bf16u(v.w - bf16f(v.w)) << 16);
    *(uint2*)(g_Ahi + idx) = make_uint2(hi01, hi23);
    *(uint2*)(g_Alo + idx) = make_uint2(lo01, lo23);
}

// ---------------------------------------------------------------------------
// Fused: column partial sums (blocks 0..127), row sums (128..1151),
// precompute F/G/ACR (1152..1232)
// ---------------------------------------------------------------------------
__global__ void __launch_bounds__(256) fused_sums_kernel(const float* __restrict__ W,
                                                         const float* __restrict__ W1,
                                                         const float* __restrict__ b1) {
    int b = blockIdx.x;
    int tid = threadIdx.x;
    if (b < 128) {
        int rg  = b >> 2;
        int col = (b & 3) * 256 + tid;
        int r0  = rg * 32;
        float s = 0.f;
#pragma unroll
        for (int r = 0; r < 32; r++) s += W[(r0 + r) * N_U + col];
        g_colpart[rg][col] = s;
    } else if (b < 128 + 1024) {
        __shared__ float red[8];
        int row = b - 128;
        float4 v = *(const float4*)(W + row * N_U + tid * 4);
        float s = v.x + v.y + v.z + v.w;
#pragma unroll
        for (int o = 16; o > 0; o >>= 1) s += __shfl_xor_sync(0xffffffffu, s, o);
        if ((tid & 31) == 0) red[tid >> 5] = s;
        __syncthreads();
        if (tid == 0) {
            float t = 0.f;
#pragma unroll
            for (int i = 0; i < 8; i++) t += red[i];
            g_rowsum[row] = t;
        }
    } else {
        int idx = (b - 1152) * 256 + tid;
        if (idx < N_U * H) {
            int i = idx / H, h = idx % H;
            float acc = 0.f;
#pragma unroll
            for (int t = 0; t < 10; t++) {
                float coef = W1[(3 + t) * H + h] + W1[(43 + t) * H + h]
                           - W1[(23 + t) * H + h] * INV1023;
                if ((i >> (9 - t)) & 1) acc += coef;
            }
            g_F[i][h] = acc;
        } else if (idx < 2 * N_U * H) {
            int r = idx - N_U * H;
            int j = r / H, h = r % H;
            float acc = b1[h];
#pragma unroll
            for (int s = 0; s < 10; s++) {
                float coef = W1[(13 + s) * H + h] + W1[(33 + s) * H + h]
                           - W1[(53 + s) * H + h] * INV1023;
                if ((j >> (9 - s)) & 1) acc += coef;
                acc += (512.f * INV1023) * (W1[(23 + s) * H + h] + W1[(53 + s) * H + h]);
            }
            g_G[j][h] = acc;                // padded row (12), cols 10-11 unused
        } else if (idx < 2 * N_U * H + H) {
            int h = idx - 2 * N_U * H;
            g_ACR[0][h] = W1[h] - (W1[H + h] + W1[2 * H + h]) * INV1023;
            g_ACR[1][h] = W1[H + h] * INV1023;
            g_ACR[2][h] = W1[2 * H + h] * INV1023;
        }
    }
}

__global__ void __launch_bounds__(256) colsum_kernel() {
    int col = blockIdx.x * 256 + threadIdx.x;
    float s = 0.f;
#pragma unroll
    for (int b = 0; b < 32; b++) s += g_colpart[b][col];
    g_colsum[col] = s;
}

// ---------------------------------------------------------------------------
// Per-cell MLP -> g_NW.  Two columns per thread; W2 transposed+padded in smem
// and loaded with vector LDS (3 loads per k instead of 10 scalar).
// grid 2048: block b -> i = b>>1, columns (b&1)*512 + tid and +256.
// ---------------------------------------------------------------------------
__global__ void __launch_bounds__(256) mlp_kernel(const float* __restrict__ W,
                                                  const float* __restrict__ W2,
                                                  const float* __restrict__ b2,
                                                  const float* __restrict__ W3,
                                                  const float* __restrict__ b3) {
    __shared__ __align__(16) float sW2T[H][12];   // [k][h] transposed, padded
    __shared__ __align__(16) float sL1[4][12];    // rows: A, C, R, F (padded)
    __shared__ float sB2[H], sW3[H];
    __shared__ float sb3, srs;
    int tid = threadIdx.x;
    int i  = blockIdx.x >> 1;
    int jh = blockIdx.x & 1;

    if (tid < H * H) sW2T[tid % H][tid / H] = W2[tid];      // W2[h][k] -> sW2T[k][h]
    else if (tid < H * H + 24) {
        int r = tid - H * H;                                 // zero padding lanes
        sW2T[r % 2 ? (r / 2) : (r / 2)][10 + (r & 1)] = 0.f; // cols 10,11 of first rows
    }
    if (tid >= 128 && tid < 128 + 48) {
        int r = tid - 128;                                   // init sL1 4x12
        int row = r / 12, col = r % 12;
        float v = 0.f;
        if (col < H) {
            if (row < 3) v = g_ACR[row][col];
            else         v = g_F[i][col];
        }
        sL1[row][col] = v;
    }
    if (tid < H) { sB2[tid] = b2[tid]; sW3[tid] = W3[tid * 21]; }
    if (tid == 0) { sb3 = b3[0]; srs = g_rowsum[i]; }
    __syncthreads();

    float rs = srs;
    int j0 = jh * 512 + tid;
    int j1 = j0 + 256;

    float w0 = W[i * N_U + j0];
    float w1 = W[i * N_U + j1];
    float cs0 = g_colsum[j0];
    float cs1 = g_colsum[j1];

    // layer 1 (vectorized over h via float4 on padded arrays)
    float z0[12], z1[12];
    const float4* A4 = (const float4*)sL1[0];
    const float4* C4 = (const float4*)sL1[1];
    const float4* R4 = (const float4*)sL1[2];
    const float4* F4 = (const float4*)sL1[3];
    const float4* G40 = (const float4*)g_G[j0];
    const float4* G41 = (const float4*)g_G[j1];
#pragma unroll
    for (int q = 0; q < 3; q++) {
        float4 a = A4[q], cc = C4[q], r = R4[q], f = F4[q];
        float4 g0 = G40[q], g1 = G41[q];
        z0[q * 4 + 0] = fmaxf(fmaf(a.x, w0, fmaf(cc.x, cs0, fmaf(r.x, rs, f.x + g0.x))), 0.f);
        z0[q * 4 + 1] = fmaxf(fmaf(a.y, w0, fmaf(cc.y, cs0, fmaf(r.y, rs, f.y + g0.y))), 0.f);
        z0[q * 4 + 2] = fmaxf(fmaf(a.z, w0, fmaf(cc.z, cs0, fmaf(r.z, rs, f.z + g0.z))), 0.f);
        z0[q * 4 + 3] = fmaxf(fmaf(a.w, w0, fmaf(cc.w, cs0, fmaf(r.w, rs, f.w + g0.w))), 0.f);
        z1[q * 4 + 0] = fmaxf(fmaf(a.x, w1, fmaf(cc.x, cs1, fmaf(r.x, rs, f.x + g1.x))), 0.f);
        z1[q * 4 + 1] = fmaxf(fmaf(a.y, w1, fmaf(cc.y, cs1, fmaf(r.y, rs, f.y + g1.y))), 0.f);
        z1[q * 4 + 2] = fmaxf(fmaf(a.z, w1, fmaf(cc.z, cs1, fmaf(r.z, rs, f.z + g1.z))), 0.f);
        z1[q * 4 + 3] = fmaxf(fmaf(a.w, w1, fmaf(cc.w, cs1, fmaf(r.w, rs, f.w + g1.w))), 0.f);
    }

    // layers 2+3: y_k = relu(b2_k + z . W2T[k]) ; upd += y_k * W3[k][0]
    float upd0 = sb3, upd1 = sb3;
#pragma unroll
    for (int k = 0; k < H; k++) {
        const float4* w4 = (const float4*)sW2T[k];
        float4 wa = w4[0], wb = w4[1];
        float2 wc = *(const float2*)&sW2T[k][8];
        float y0 = sB2[k], y1 = sB2[k];
        y0 = fmaf(z0[0], wa.x, y0); y1 = fmaf(z1[0], wa.x, y1);
        y0 = fmaf(z0[1], wa.y, y0); y1 = fmaf(z1[1], wa.y, y1);
        y0 = fmaf(z0[2], wa.z, y0); y1 = fmaf(z1[2], wa.z, y1);
        y0 = fmaf(z0[3], wa.w, y0); y1 = fmaf(z1[3], wa.w, y1);
        y0 = fmaf(z0[4], wb.x, y0); y1 = fmaf(z1[4], wb.x, y1);
        y0 = fmaf(z0[5], wb.y, y0); y1 = fmaf(z1[5], wb.y, y1);
        y0 = fmaf(z0[6], wb.z, y0); y1 = fmaf(z1[6], wb.z, y1);
        y0 = fmaf(z0[7], wb.w, y0); y1 = fmaf(z1[7], wb.w, y1);
        y0 = fmaf(z0[8], wc.x, y0); y1 = fmaf(z1[8], wc.x, y1);
        y0 = fmaf(z0[9], wc.y, y0); y1 = fmaf(z1[9], wc.y, y1);
        float w3k = sW3[k];
        upd0 = fmaf(fmaxf(y0, 0.f), w3k, upd0);
        upd1 = fmaf(fmaxf(y1, 0.f), w3k, upd1);
    }
    g_NW[i * N_U + j0] = w0 + upd0;
    g_NW[i * N_U + j1] = w1 + upd1;
}

// ---------------------------------------------------------------------------
// Transpose + split NW -> g_Bhi/g_Blo [n][k]
// ---------------------------------------------------------------------------
__global__ void __launch_bounds__(256) transpose_split_kernel() {
    __shared__ float tile[32][33];
    int bx = blockIdx.x, by = blockIdx.y;
    int tx = threadIdx.x, ty = threadIdx.y;           // 32 x 8
    int i0 = by * 32, j0 = bx * 32;
#pragma unroll
    for (int r = 0; r < 4; r++)
        tile[ty * 4 + r][tx] = g_NW[(i0 + ty * 4 + r) * N_U + j0 + tx];
    __syncthreads();
#pragma unroll
    for (int r = 0; r < 4; r++) {
        int j = j0 + ty * 4 + r;
        int i = i0 + tx;
        float v  = tile[tx][ty * 4 + r];
        float hi = bf16f(v);
        g_Bhi[j * N_U + i] = bf16u(v);
        g_Blo[j * N_U + i] = bf16u(v - hi);
    }
}

// ---------------------------------------------------------------------------
// GEMM: out = relu( Ahi*Bhi + Ahi*Blo + Alo*Bhi ), bf16 mma.sync.
// BM=128, BN=256, BK=32, 256 threads (8 warps, 2m x 4n), warp tile 64x64.
// 4-stage cp.async pipeline; padded smem rows (40 bf16 = 80B) conflict-free.
// ---------------------------------------------------------------------------
#define BM 128
#define BN 256
#define BK 32
#define STAGES 4
#define AROW 40
#define ABYTES (BM * AROW * 2)           // 10240
#define BBYTES (BN * AROW * 2)           // 20480
#define STBYTES (ABYTES + BBYTES)        // 30720
#define SMEM_GEMM (STAGES * STBYTES)     // 122880

__global__ void __launch_bounds__(256, 1) gemm_mma_kernel(float* __restrict__ out) {
    extern __shared__ char smem[];
    uint32_t sb = smem_u32(smem);
    int tid  = threadIdx.x;
    int wid  = tid >> 5;
    int lane = tid & 31;

    int mt = blockIdx.x & 31;            // 32 m-tiles
    int nt = blockIdx.x >> 5;            // 4 n-tiles
    int mw = wid & 1;                    // warp m (2)
    int nw = wid >> 1;                   // warp n (4)

    const unsigned short* Aseg[3];
    const unsigned short* Bseg[3];
    Aseg[0] = g_Ahi + (size_t)(mt * BM) * N_U;
    Aseg[1] = Aseg[0];
    Aseg[2] = g_Alo + (size_t)(mt * BM) * N_U;
    Bseg[0] = g_Bhi + (size_t)(nt * BN) * N_U;
    Bseg[1] = g_Blo + (size_t)(nt * BN) * N_U;
    Bseg[2] = Bseg[0];

    float c[4][8][4];
#pragma unroll
    for (int f = 0; f < 4; f++)
#pragma unroll
        for (int n = 0; n < 8; n++)
#pragma unroll
            for (int q = 0; q < 4; q++) c[f][n][q] = 0.f;

    const int ITERS = 96;

    auto load_stage = [&](int it, int st) {
        int seg = it >> 5;
        int k0  = (it & 31) * BK;
        uint32_t abase = sb + st * STBYTES;
        uint32_t bbase = abase + ABYTES;
        const unsigned short* Ag = Aseg[seg];
        const unsigned short* Bg = Bseg[seg];
#pragma unroll
        for (int q = 0; q < 2; q++) {
            int chunk = tid + q * 256;
            int row = chunk >> 2;
            int off = (chunk & 3) * 8;
            CP_ASYNC16(abase + row * (AROW * 2) + off * 2,
                       (const char*)(Ag + (size_t)row * N_U + k0 + off));
        }
#pragma unroll
        for (int q = 0; q < 4; q++) {
            int chunk = tid + q * 256;
            int row = chunk >> 2;
            int off = (chunk & 3) * 8;
            CP_ASYNC16(bbase + row * (AROW * 2) + off * 2,
                       (const char*)(Bg + (size_t)row * N_U + k0 + off));
        }
    };

#pragma unroll
    for (int s = 0; s < STAGES - 1; s++) {
        load_stage(s, s);
        CP_COMMIT();
    }

    int lrow = lane & 15;
    int lcol = (lane >> 4) * 16;

    for (int i = 0; i < ITERS; i++) {
        CP_WAIT(2);
        __syncthreads();                 // single barrier: data ready + slot reuse safe

        int nx = i + STAGES - 1;
        if (nx < ITERS) load_stage(nx, nx & (STAGES - 1));
        CP_COMMIT();

        int st = i & (STAGES - 1);
        uint32_t abase = sb + st * STBYTES;
        uint32_t bbase = abase + ABYTES;

#pragma unroll
        for (int ks = 0; ks < 2; ks++) {
            uint32_t a[4][4];
#pragma unroll
            for (int f = 0; f < 4; f++)
                LDMATRIX_X4(a[f][0], a[f][1], a[f][2], a[f][3],
                    abase + (mw * 64 + f * 16 + lrow) * (AROW * 2) + ks * 32 + lcol);
            uint32_t b[8][2];
#pragma unroll
            for (int g = 0; g < 4; g++) {
                uint32_t r0, r1, r2, r3;
                LDMATRIX_X4(r0, r1, r2, r3,
                    bbase + (nw * 64 + g * 16 + lrow) * (AROW * 2) + ks * 32 + lcol);
                b[2 * g][0] = r0;  b[2 * g][1] = r2;
                b[2 * g + 1][0] = r1;  b[2 * g + 1][1] = r3;
            }
#pragma unroll
            for (int f = 0; f < 4; f++)
#pragma unroll
                for (int n = 0; n < 8; n++)
                    MMA_BF16(c[f][n][0], c[f][n][1], c[f][n][2], c[f][n][3],
                             a[f][0], a[f][1], a[f][2], a[f][3], b[n][0], b[n][1]);
        }
    }

    // Epilogue: relu + store
    int rbase = mt * BM + mw * 64 + (lane >> 2);
    int cbase = nt * BN + nw * 64 + (lane & 3) * 2;
#pragma unroll
    for (int f = 0; f < 4; f++) {
#pragma unroll
        for (int n = 0; n < 8; n++) {
            int r = rbase + f * 16;
            int cc = cbase + n * 8;
            float2 v0, v1;
            v0.x = fmaxf(c[f][n][0], 0.f);
            v0.y = fmaxf(c[f][n][1], 0.f);
            v1.x = fmaxf(c[f][n][2], 0.f);
            v1.y = fmaxf(c[f][n][3], 0.f);
            *(float2*)(out + (size_t)r * N_U + cc)       = v0;
            *(float2*)(out + (size_t)(r + 8) * N_U + cc) = v1;
        }
    }
}

// ---------------------------------------------------------------------------
// Row softmax in-place
// ---------------------------------------------------------------------------
__global__ void __launch_bounds__(256) softmax_kernel(float* __restrict__ out) {
    __shared__ float redm[8];
    __shared__ float reds[8];
    __shared__ float bval[2];
    int row = blockIdx.x, tid = threadIdx.x;
    int lane = tid & 31, wid = tid >> 5;

    float4 v = *(float4*)(out + row * N_U + tid * 4);
    float m = fmaxf(fmaxf(v.x, v.y), fmaxf(v.z, v.w));
#pragma unroll
    for (int o = 16; o > 0; o >>= 1) m = fmaxf(m, __shfl_xor_sync(0xffffffffu, m, o));
    if (lane == 0) redm[wid] = m;
    __syncthreads();
    if (tid == 0) {
        float t = redm[0];
#pragma unroll
        for (int i = 1; i < 8; i++) t = fmaxf(t, redm[i]);
        bval[0] = t;
    }
    __syncthreads();
    m = bval[0];
    v.x = __expf(v.x - m); v.y = __expf(v.y - m);
    v.z = __expf(v.z - m); v.w = __expf(v.w - m);
    float s = v.x + v.y + v.z + v.w;
#pragma unroll
    for (int o = 16; o > 0; o >>= 1) s += __shfl_xor_sync(0xffffffffu, s, o);
    if (lane == 0) reds[wid] = s;
    __syncthreads();
    if (tid == 0) {
        float t = 0.f;
#pragma unroll
        for (int i = 0; i < 8; i++) t += reds[i];
        bval[1] = 1.f / t;
    }
    __syncthreads();
    float inv = bval[1];
    v.x *= inv; v.y *= inv; v.z *= inv; v.w *= inv;
    *(float4*)(out + row * N_U + tid * 4) = v;
}

// ---------------------------------------------------------------------------
// Entry point — GEMM is the 6th launch so ncu (-s 5 -c 1) profiles it.
// ---------------------------------------------------------------------------
extern "C" void kernel_launch(void* const* d_in, const int* in_sizes, int n_in,
                              void* d_out, int out_size) {
    const float* X      = (const float*)d_in[0];
    const float* weight = (const float*)d_in[1];
    const float* W1     = (const float*)d_in[3];
    const float* b1     = (const float*)d_in[4];
    const float* W2     = (const float*)d_in[5];
    const float* b2     = (const float*)d_in[6];
    const float* W3     = (const float*)d_in[7];
    const float* b3     = (const float*)d_in[8];
    float* out = (float*)d_out;

    static bool attr_done = false;
    if (!attr_done) {
        cudaFuncSetAttribute(gemm_mma_kernel,
                             cudaFuncAttributeMaxDynamicSharedMemorySize, SMEM_GEMM);
        attr_done = true;
    }

    split_x_kernel<<<BATCH * N_U / 1024, 256>>>(X);                     // 1
    fused_sums_kernel<<<128 + 1024 + 81, 256>>>(weight, W1, b1);        // 2
    colsum_kernel<<<4, 256>>>();                                        // 3
    mlp_kernel<<<2048, 256>>>(weight, W2, b2, W3, b3);                  // 4
    transpose_split_kernel<<<dim3(32, 32), dim3(32, 8)>>>();            // 5
    gemm_mma_kernel<<<128, 256, SMEM_GEMM>>>(out);                      // 6  <- profiled
    softmax_kernel<<<BATCH, 256>>>(out);                                // 7
}

// round 8
// speedup vs baseline: 1.2278x; 1.0633x over previous
#include <cuda_runtime.h>
#include <cuda_bf16.h>
#include <cstdint>

// Problem constants
#define N_U   1024
#define BATCH 4096
#define H     10
#define INV1023 (1.0f / 1023.0f)

// ---------------------------------------------------------------------------
// Scratch (device globals)
// ---------------------------------------------------------------------------
__device__ float g_colpart[32][N_U];
__device__ float g_colsum[N_U];
__device__ float g_rowsum[N_U];
__device__ float g_F[N_U][H];
__device__ __align__(16) float g_G[N_U][12];      // padded to 12 for float4 loads
__device__ float g_ACR[3][H];
__device__ __align__(256) float g_NW[N_U * N_U];                 // new_weight [k][n]

// Split operands (bf16 as ushort)
__device__ __align__(256) unsigned short g_Ahi[BATCH * N_U];     // 8 MB
__device__ __align__(256) unsigned short g_Alo[BATCH * N_U];     // 8 MB
__device__ __align__(256) unsigned short g_Bhi[N_U * N_U];       // 2 MB  [n][k]
__device__ __align__(256) unsigned short g_Blo[N_U * N_U];       // 2 MB  [n][k]

// ---------------------------------------------------------------------------
// Helpers
// ---------------------------------------------------------------------------
__device__ __forceinline__ uint32_t smem_u32(const void* p) {
    uint32_t a;
    asm("{ .reg .u64 t; cvta.to.shared.u64 t, %1; cvt.u32.u64 %0, t; }" : "=r"(a) : "l"(p));
    return a;
}
__device__ __forceinline__ unsigned short bf16u(float x) {
    return __bfloat16_as_ushort(__float2bfloat16_rn(x));
}
__device__ __forceinline__ float bf16f(float x) {
    return __bfloat162float(__float2bfloat16_rn(x));
}

#define CP_ASYNC16(dst, src) \
    asm volatile("cp.async.cg.shared.global [%0], [%1], 16;" :: "r"(dst), "l"(src))
#define CP_COMMIT() asm volatile("cp.async.commit_group;")
#define CP_WAIT(n)  asm volatile("cp.async.wait_group %0;" :: "n"(n))

#define LDMATRIX_X4(r0, r1, r2, r3, addr) \
    asm volatile("ldmatrix.sync.aligned.m8n8.x4.shared.b16 {%0,%1,%2,%3}, [%4];" \
        : "=r"(r0), "=r"(r1), "=r"(r2), "=r"(r3) : "r"(addr))

#define MMA_BF16(c0, c1, c2, c3, a0, a1, a2, a3, b0, b1) \
    asm volatile("mma.sync.aligned.m16n8k16.row.col.f32.bf16.bf16.f32 " \
        "{%0,%1,%2,%3}, {%4,%5,%6,%7}, {%8,%9}, {%0,%1,%2,%3};" \
        : "+f"(c0), "+f"(c1), "+f"(c2), "+f"(c3) \
        : "r"(a0), "r"(a1), "r"(a2), "r"(a3), "r"(b0), "r"(b1))

// ---------------------------------------------------------------------------
// Split X -> g_Ahi/g_Alo [m][k]
// ---------------------------------------------------------------------------
__global__ void __launch_bounds__(256) split_x_kernel(const float* __restrict__ X) {
    int gid = blockIdx.x * 256 + threadIdx.x;
    int idx = gid * 4;
    float4 v = *(const float4*)(X + idx);
    uint32_t hi01 = (uint32_t)bf16u(v.x) | ((uint32_t)bf16u(v.y) << 16);
    uint32_t hi23 = (uint32_t)bf16u(v.z) | ((uint32_t)bf16u(v.w) << 16);
    uint32_t lo01 = (uint32_t)bf16u(v.x - bf16f(v.x)) | ((uint32_t)bf16u(v.y - bf16f(v.y)) << 16);
    uint32_t lo23 = (uint32_t)bf16u(v.z - bf16f(v.z)) | ((uint32_t)bf16u(v.w - bf16f(v.w)) << 16);
    *(uint2*)(g_Ahi + idx) = make_uint2(hi01, hi23);
    *(uint2*)(g_Alo + idx) = make_uint2(lo01, lo23);
}

// ---------------------------------------------------------------------------
// Fused: column partial sums (blocks 0..127), row sums (128..1151),
// precompute F/G/ACR (1152..1232)
// ---------------------------------------------------------------------------
__global__ void __launch_bounds__(256) fused_sums_kernel(const float* __restrict__ W,
                                                         const float* __restrict__ W1,
                                                         const float* __restrict__ b1) {
    int b = blockIdx.x;
    int tid = threadIdx.x;
    if (b < 128) {
        int rg  = b >> 2;
        int col = (b & 3) * 256 + tid;
        int r0  = rg * 32;
        float s = 0.f;
#pragma unroll
        for (int r = 0; r < 32; r++) s += W[(r0 + r) * N_U + col];
        g_colpart[rg][col] = s;
    } else if (b < 128 + 1024) {
        __shared__ float red[8];
        int row = b - 128;
        float4 v = *(const float4*)(W + row * N_U + tid * 4);
        float s = v.x + v.y + v.z + v.w;
#pragma unroll
        for (int o = 16; o > 0; o >>= 1) s += __shfl_xor_sync(0xffffffffu, s, o);
        if ((tid & 31) == 0) red[tid >> 5] = s;
        __syncthreads();
        if (tid == 0) {
            float t = 0.f;
#pragma unroll
            for (int i = 0; i < 8; i++) t += red[i];
            g_rowsum[row] = t;
        }
    } else {
        int idx = (b - 1152) * 256 + tid;
        if (idx < N_U * H) {
            int i = idx / H, h = idx % H;
            float acc = 0.f;
#pragma unroll
            for (int t = 0; t < 10; t++) {
                float coef = W1[(3 + t) * H + h] + W1[(43 + t) * H + h]
                           - W1[(23 + t) * H + h] * INV1023;
                if ((i >> (9 - t)) & 1) acc += coef;
            }
            g_F[i][h] = acc;
        } else if (idx < 2 * N_U * H) {
            int r = idx - N_U * H;
            int j = r / H, h = r % H;
            float acc = b1[h];
#pragma unroll
            for (int s = 0; s < 10; s++) {
                float coef = W1[(13 + s) * H + h] + W1[(33 + s) * H + h]
                           - W1[(53 + s) * H + h] * INV1023;
                if ((j >> (9 - s)) & 1) acc += coef;
                acc += (512.f * INV1023) * (W1[(23 + s) * H + h] + W1[(53 + s) * H + h]);
            }
            g_G[j][h] = acc;                // padded row (12); cols 10-11 stay 0
        } else if (idx < 2 * N_U * H + H) {
            int h = idx - 2 * N_U * H;
            g_ACR[0][h] = W1[h] - (W1[H + h] + W1[2 * H + h]) * INV1023;
            g_ACR[1][h] = W1[H + h] * INV1023;
            g_ACR[2][h] = W1[2 * H + h] * INV1023;
        }
    }
}

__global__ void __launch_bounds__(256) colsum_kernel() {
    int col = blockIdx.x * 256 + threadIdx.x;
    float s = 0.f;
#pragma unroll
    for (int b = 0; b < 32; b++) s += g_colpart[b][col];
    g_colsum[col] = s;
}

// ---------------------------------------------------------------------------
// Per-cell MLP -> g_NW.  One block per row i; FOUR columns per thread.
// W2 transposed+padded in smem; layer-1 coefs in smem (all broadcast reads).
// ---------------------------------------------------------------------------
__global__ void __launch_bounds__(256) mlp_kernel(const float* __restrict__ W,
                                                  const float* __restrict__ W2,
                                                  const float* __restrict__ b2,
                                                  const float* __restrict__ W3,
                                                  const float* __restrict__ b3) {
    __shared__ __align__(16) float sW2T[H][12];   // [k][h] transposed, padded
    __shared__ __align__(16) float sL1[4][12];    // rows: A, C, R, F (padded)
    __shared__ float sB2[H], sW3[H];
    __shared__ float sb3, srs;
    int tid = threadIdx.x;
    int i = blockIdx.x;

    if (tid < 120) {                              // clean init, no OOB
        int k = tid / 12, h = tid % 12;
        sW2T[k][h] = (h < H) ? W2[h * H + k] : 0.f;
    }
    if (tid >= 128 && tid < 176) {
        int r = tid - 128;
        int row = r / 12, col = r % 12;
        float v = 0.f;
        if (col < H) v = (row < 3) ? g_ACR[row][col] : g_F[i][col];
        sL1[row][col] = v;
    }
    if (tid < H) { sB2[tid] = b2[tid]; sW3[tid] = W3[tid * 21]; }
    if (tid == 0) { sb3 = b3[0]; srs = g_rowsum[i]; }
    __syncthreads();

    float rs = srs;
    float w[4], cs[4];
#pragma unroll
    for (int c = 0; c < 4; c++) {
        int j = c * 256 + tid;
        w[c]  = W[i * N_U + j];
        cs[c] = g_colsum[j];
    }

    float z[4][12];
    const float4* A4 = (const float4*)sL1[0];
    const float4* C4 = (const float4*)sL1[1];
    const float4* R4 = (const float4*)sL1[2];
    const float4* F4 = (const float4*)sL1[3];
#pragma unroll
    for (int q = 0; q < 3; q++) {
        float4 a = A4[q], cc = C4[q], r = R4[q], f = F4[q];
#pragma unroll
        for (int c = 0; c < 4; c++) {
            int j = c * 256 + tid;
            float4 g = ((const float4*)g_G[j])[q];
            z[c][q * 4 + 0] = fmaxf(fmaf(a.x, w[c], fmaf(cc.x, cs[c], fmaf(r.x, rs, f.x + g.x))), 0.f);
            z[c][q * 4 + 1] = fmaxf(fmaf(a.y, w[c], fmaf(cc.y, cs[c], fmaf(r.y, rs, f.y + g.y))), 0.f);
            z[c][q * 4 + 2] = fmaxf(fmaf(a.z, w[c], fmaf(cc.z, cs[c], fmaf(r.z, rs, f.z + g.z))), 0.f);
            z[c][q * 4 + 3] = fmaxf(fmaf(a.w, w[c], fmaf(cc.w, cs[c], fmaf(r.w, rs, f.w + g.w))), 0.f);
        }
    }

    float upd[4] = {sb3, sb3, sb3, sb3};
#pragma unroll
    for (int k = 0; k < H; k++) {
        const float4* w4 = (const float4*)sW2T[k];
        float4 wa = w4[0], wb = w4[1];
        float2 wc = *(const float2*)&sW2T[k][8];
        float bk = sB2[k], w3k = sW3[k];
#pragma unroll
        for (int c = 0; c < 4; c++) {
            float y = bk;
            y = fmaf(z[c][0], wa.x, y);
            y = fmaf(z[c][1], wa.y, y);
            y = fmaf(z[c][2], wa.z, y);
            y = fmaf(z[c][3], wa.w, y);
            y = fmaf(z[c][4], wb.x, y);
            y = fmaf(z[c][5], wb.y, y);
            y = fmaf(z[c][6], wb.z, y);
            y = fmaf(z[c][7], wb.w, y);
            y = fmaf(z[c][8], wc.x, y);
            y = fmaf(z[c][9], wc.y, y);
            upd[c] = fmaf(fmaxf(y, 0.f), w3k, upd[c]);
        }
    }
#pragma unroll
    for (int c = 0; c < 4; c++) {
        int j = c * 256 + tid;
        g_NW[i * N_U + j] = w[c] + upd[c];
    }
}

// ---------------------------------------------------------------------------
// Transpose + split NW -> g_Bhi/g_Blo [n][k]
// ---------------------------------------------------------------------------
__global__ void __launch_bounds__(256) transpose_split_kernel() {
    __shared__ float tile[32][33];
    int bx = blockIdx.x, by = blockIdx.y;
    int tx = threadIdx.x, ty = threadIdx.y;           // 32 x 8
    int i0 = by * 32, j0 = bx * 32;
#pragma unroll
    for (int r = 0; r < 4; r++)
        tile[ty * 4 + r][tx] = g_NW[(i0 + ty * 4 + r) * N_U + j0 + tx];
    __syncthreads();
#pragma unroll
    for (int r = 0; r < 4; r++) {
        int j = j0 + ty * 4 + r;
        int i = i0 + tx;
        float v  = tile[tx][ty * 4 + r];
        float hi = bf16f(v);
        g_Bhi[j * N_U + i] = bf16u(v);
        g_Blo[j * N_U + i] = bf16u(v - hi);
    }
}

// ---------------------------------------------------------------------------
// GEMM: out = relu( Ahi*Bhi + Ahi*Blo + Alo*Bhi ), bf16 mma.sync.
// BM=112, BN=256 -> grid 37x4 = 148 CTAs (one perfectly balanced wave).
// 256 threads, 8 warps: each warp covers all 112 rows x 32 cols (7x4 frags).
// M padded to 4144: A loads clamp row, stores guarded.
// 4-stage cp.async pipeline; 80B padded smem rows.
// ---------------------------------------------------------------------------
#define BM 112
#define BN 256
#define BK 32
#define STAGES 4
#define AROW 40
#define ABYTES (BM * AROW * 2)           // 8960
#define BBYTES (BN * AROW * 2)           // 20480
#define STBYTES (ABYTES + BBYTES)        // 29440
#define SMEM_GEMM (STAGES * STBYTES)     // 117760

__global__ void __launch_bounds__(256, 1) gemm_mma_kernel(float* __restrict__ out) {
    extern __shared__ char smem[];
    uint32_t sb = smem_u32(smem);
    int tid  = threadIdx.x;
    int wid  = tid >> 5;
    int lane = tid & 31;

    int mt = blockIdx.x % 37;            // 37 m-tiles of 112 rows
    int nt = blockIdx.x / 37;            // 4 n-tiles of 256 cols
    int nw = wid;                        // warp covers cols nw*32..nw*32+31

    const unsigned short* Aseg[3];       // absolute bases (row clamped at load)
    const unsigned short* Bseg[3];
    Aseg[0] = g_Ahi;  Aseg[1] = g_Ahi;  Aseg[2] = g_Alo;
    Bseg[0] = g_Bhi + (size_t)(nt * BN) * N_U;
    Bseg[1] = g_Blo + (size_t)(nt * BN) * N_U;
    Bseg[2] = Bseg[0];

    float c[7][4][4];
#pragma unroll
    for (int f = 0; f < 7; f++)
#pragma unroll
        for (int n = 0; n < 4; n++)
#pragma unroll
            for (int q = 0; q < 4; q++) c[f][n][q] = 0.f;

    const int ITERS = 96;

    auto load_stage = [&](int it, int st) {
        int seg = it >> 5;
        int k0  = (it & 31) * BK;
        uint32_t abase = sb + st * STBYTES;
        uint32_t bbase = abase + ABYTES;
        const unsigned short* Ag = Aseg[seg];
        const unsigned short* Bg = Bseg[seg];
        // A: 448 16B chunks (112 rows x 4)
#pragma unroll
        for (int q = 0; q < 2; q++) {
            int chunk = tid + q * 256;
            if (chunk < BM * 4) {
                int row = chunk >> 2;
                int off = (chunk & 3) * 8;
                int grow = mt * BM + row;
                if (grow > 4095) grow = 4095;           // clamp (pad region)
                CP_ASYNC16(abase + row * (AROW * 2) + off * 2,
                           (const char*)(Ag + (size_t)grow * N_U + k0 + off));
            }
        }
        // B: 1024 16B chunks (256 rows x 4)
#pragma unroll
        for (int q = 0; q < 4; q++) {
            int chunk = tid + q * 256;
            int row = chunk >> 2;
            int off = (chunk & 3) * 8;
            CP_ASYNC16(bbase + row * (AROW * 2) + off * 2,
                       (const char*)(Bg + (size_t)row * N_U + k0 + off));
        }
    };

#pragma unroll
    for (int s = 0; s < STAGES - 1; s++) {
        load_stage(s, s);
        CP_COMMIT();
    }

    int lrow = lane & 15;
    int lcol = (lane >> 4) * 16;

    for (int i = 0; i < ITERS; i++) {
        CP_WAIT(2);
        __syncthreads();

        int nx = i + STAGES - 1;
        if (nx < ITERS) load_stage(nx, nx & (STAGES - 1));
        CP_COMMIT();

        int st = i & (STAGES - 1);
        uint32_t abase = sb + st * STBYTES;
        uint32_t bbase = abase + ABYTES;

#pragma unroll
        for (int ks = 0; ks < 2; ks++) {
            uint32_t a[7][4];
#pragma unroll
            for (int f = 0; f < 7; f++)
                LDMATRIX_X4(a[f][0], a[f][1], a[f][2], a[f][3],
                    abase + (f * 16 + lrow) * (AROW * 2) + ks * 32 + lcol);
            uint32_t b[4][2];
#pragma unroll
            for (int g = 0; g < 2; g++) {
                uint32_t r0, r1, r2, r3;
                LDMATRIX_X4(r0, r1, r2, r3,
                    bbase + (nw * 32 + g * 16 + lrow) * (AROW * 2) + ks * 32 + lcol);
                b[2 * g][0] = r0;  b[2 * g][1] = r2;
                b[2 * g + 1][0] = r1;  b[2 * g + 1][1] = r3;
            }
#pragma unroll
            for (int f = 0; f < 7; f++)
#pragma unroll
                for (int n = 0; n < 4; n++)
                    MMA_BF16(c[f][n][0], c[f][n][1], c[f][n][2], c[f][n][3],
                             a[f][0], a[f][1], a[f][2], a[f][3], b[n][0], b[n][1]);
        }
    }

    // Epilogue: relu + guarded store
    int cbase = nt * BN + nw * 32 + (lane & 3) * 2;
#pragma unroll
    for (int f = 0; f < 7; f++) {
        int r = mt * BM + f * 16 + (lane >> 2);
#pragma unroll
        for (int n = 0; n < 4; n++) {
            int cc = cbase + n * 8;
            if (r < BATCH) {
                float2 v0;
                v0.x = fmaxf(c[f][n][0], 0.f);
                v0.y = fmaxf(c[f][n][1], 0.f);
                *(float2*)(out + (size_t)r * N_U + cc) = v0;
            }
            if (r + 8 < BATCH) {
                float2 v1;
                v1.x = fmaxf(c[f][n][2], 0.f);
                v1.y = fmaxf(c[f][n][3], 0.f);
                *(float2*)(out + (size_t)(r + 8) * N_U + cc) = v1;
            }
        }
    }
}

// ---------------------------------------------------------------------------
// Row softmax in-place
// ---------------------------------------------------------------------------
__global__ void __launch_bounds__(256) softmax_kernel(float* __restrict__ out) {
    __shared__ float redm[8];
    __shared__ float reds[8];
    __shared__ float bval[2];
    int row = blockIdx.x, tid = threadIdx.x;
    int lane = tid & 31, wid = tid >> 5;

    float4 v = *(float4*)(out + row * N_U + tid * 4);
    float m = fmaxf(fmaxf(v.x, v.y), fmaxf(v.z, v.w));
#pragma unroll
    for (int o = 16; o > 0; o >>= 1) m = fmaxf(m, __shfl_xor_sync(0xffffffffu, m, o));
    if (lane == 0) redm[wid] = m;
    __syncthreads();
    if (tid == 0) {
        float t = redm[0];
#pragma unroll
        for (int i = 1; i < 8; i++) t = fmaxf(t, redm[i]);
        bval[0] = t;
    }
    __syncthreads();
    m = bval[0];
    v.x = __expf(v.x - m); v.y = __expf(v.y - m);
    v.z = __expf(v.z - m); v.w = __expf(v.w - m);
    float s = v.x + v.y + v.z + v.w;
#pragma unroll
    for (int o = 16; o > 0; o >>= 1) s += __shfl_xor_sync(0xffffffffu, s, o);
    if (lane == 0) reds[wid] = s;
    __syncthreads();
    if (tid == 0) {
        float t = 0.f;
#pragma unroll
        for (int i = 0; i < 8; i++) t += reds[i];
        bval[1] = 1.f / t;
    }
    __syncthreads();
    float inv = bval[1];
    v.x *= inv; v.y *= inv; v.z *= inv; v.w *= inv;
    *(float4*)(out + row * N_U + tid * 4) = v;
}

// ---------------------------------------------------------------------------
// Entry point
// ---------------------------------------------------------------------------
extern "C" void kernel_launch(void* const* d_in, const int* in_sizes, int n_in,
                              void* d_out, int out_size) {
    const float* X      = (const float*)d_in[0];
    const float* weight = (const float*)d_in[1];
    const float* W1     = (const float*)d_in[3];
    const float* b1     = (const float*)d_in[4];
    const float* W2     = (const float*)d_in[5];
    const float* b2     = (const float*)d_in[6];
    const float* W3     = (const float*)d_in[7];
    const float* b3     = (const float*)d_in[8];
    float* out = (float*)d_out;

    static bool attr_done = false;
    if (!attr_done) {
        cudaFuncSetAttribute(gemm_mma_kernel,
                             cudaFuncAttributeMaxDynamicSharedMemorySize, SMEM_GEMM);
        attr_done = true;
    }

    split_x_kernel<<<BATCH * N_U / 1024, 256>>>(X);                     // 1
    fused_sums_kernel<<<128 + 1024 + 81, 256>>>(weight, W1, b1);        // 2
    colsum_kernel<<<4, 256>>>();                                        // 3
    mlp_kernel<<<N_U, 256>>>(weight, W2, b2, W3, b3);                   // 4
    transpose_split_kernel<<<dim3(32, 32), dim3(32, 8)>>>();            // 5
    gemm_mma_kernel<<<148, 256, SMEM_GEMM>>>(out);                      // 6
    softmax_kernel<<<BATCH, 256>>>(out);                                // 7
}